// round 1
// baseline (speedup 1.0000x reference)
#include <cuda_runtime.h>
#include <math.h>

// ---------------------------------------------------------------------------
// Problem constants
// ---------------------------------------------------------------------------
#define B_  128
#define T_  64
#define D_  300
#define KP_ 304          // D padded to multiple of 16 for GEMM
#define H_  512
#define G4_ 2048         // 4*H

// ---------------------------------------------------------------------------
// Scratch buffer layout (floats). Single __device__ array -> one symbol lookup.
// ---------------------------------------------------------------------------
static constexpr size_t OFF_E   = 0;                                   // e1,e2 padded [2][8192][304]
static constexpr size_t OFF_WXP = OFF_E   + 2ull * B_ * T_ * KP_;      // padded Wx [2][304][2048]
static constexpr size_t OFF_XG  = OFF_WXP + 2ull * KP_ * G4_;          // X-part gates [4][B][T][2048]
static constexpr size_t OFF_Y   = OFF_XG  + 4ull * B_ * T_ * G4_;      // LSTM outputs [4][B][T][512]
static constexpr size_t OFF_H   = OFF_Y   + 4ull * B_ * T_ * H_;       // h state [4][B][512]
static constexpr size_t OFF_C   = OFF_H   + 4ull * B_ * H_;            // c state [4][B][512]
static constexpr size_t OFF_G   = OFF_C   + 4ull * B_ * H_;            // step gates [4][B][2048]
static constexpr size_t OFF_WYY = OFF_G   + 4ull * B_ * G4_;           // WyY [2][8192][512]
static constexpr size_t OFF_WC  = OFF_WYY + 2ull * B_ * T_ * H_;       // Wcomb [1024][1024]
static constexpr size_t OFF_UP  = OFF_WC  + 4ull * H_ * H_;            // uP4 split-K partials [8][B][1024]
static constexpr size_t OFF_AA  = OFF_UP  + 8ull * B_ * 2 * H_;        // att A input [2][B][1024]
static constexpr size_t OFF_RL  = OFF_AA  + 2ull * B_ * 2 * H_;        // r_L [2][B][512]
static constexpr size_t TOTAL_F = OFF_RL  + 2ull * B_ * H_;

__device__ float d_buf[TOTAL_F];

// ---------------------------------------------------------------------------
// Prep: pad Wx (first 300 rows of W1/W2) and build Wcomb = [[Wh,0],[Wr,Wt]]
// ---------------------------------------------------------------------------
__global__ void k_prep(float* __restrict__ WxP, float* __restrict__ Wc,
                       const float* __restrict__ W1, const float* __restrict__ W2,
                       const float* __restrict__ Wh, const float* __restrict__ Wr,
                       const float* __restrict__ Wt) {
    size_t n1 = 2ull * KP_ * G4_;
    size_t n2 = 1024ull * 1024ull;
    size_t stride = (size_t)gridDim.x * blockDim.x;
    for (size_t i = (size_t)blockIdx.x * blockDim.x + threadIdx.x; i < n1 + n2; i += stride) {
        if (i < n1) {
            int w   = (int)(i / ((size_t)KP_ * G4_));
            size_t rem = i % ((size_t)KP_ * G4_);
            int k = (int)(rem / G4_), n = (int)(rem % G4_);
            const float* W = w ? W2 : W1;
            WxP[i] = (k < D_) ? W[(size_t)k * G4_ + n] : 0.f;
        } else {
            size_t j = i - n1;
            int k = (int)(j >> 10), n = (int)(j & 1023);
            float v;
            if (k < H_) {
                v = (n < H_) ? Wh[(size_t)k * H_ + n] : 0.f;
            } else {
                int k2 = k - H_;
                v = (n < H_) ? Wr[(size_t)k2 * H_ + n] : Wt[(size_t)k2 * H_ + (n - H_)];
            }
            Wc[j] = v;
        }
    }
}

// ---------------------------------------------------------------------------
// Embedding gather (padded to KP_)
// ---------------------------------------------------------------------------
__global__ void k_gather(float* __restrict__ e, const int* __restrict__ t1,
                         const int* __restrict__ t2, const float* __restrict__ emb) {
    size_t total = 2ull * B_ * T_ * KP_;
    size_t stride = (size_t)gridDim.x * blockDim.x;
    for (size_t i = (size_t)blockIdx.x * blockDim.x + threadIdx.x; i < total; i += stride) {
        int which = (int)(i / ((size_t)B_ * T_ * KP_));
        size_t rem = i % ((size_t)B_ * T_ * KP_);
        int bt = (int)(rem / KP_), k = (int)(rem % KP_);
        int tok = (which ? t2 : t1)[bt];
        e[i] = (k < D_) ? emb[(size_t)tok * D_ + k] : 0.f;
    }
}

__global__ void k_zero(float* __restrict__ p, size_t n) {
    size_t stride = (size_t)gridDim.x * blockDim.x;
    for (size_t i = (size_t)blockIdx.x * blockDim.x + threadIdx.x; i < n; i += stride)
        p[i] = 0.f;
}

// ---------------------------------------------------------------------------
// Generic batched SGEMM: C[z] = A[z](MxK) * B[z](KxN) (+ Add[z] + bias[z])
// Tile 64x64, BK=16, 256 threads, 4x4 per thread. M,N mult of 64; K mult of 16.
// ---------------------------------------------------------------------------
struct GemmP {
    const float* A[8];
    const float* Bm[8];
    const float* Add[8];
    const float* bias[8];
    float*       C[8];
    int M, N, K, lda, ldAdd;
};

__global__ void __launch_bounds__(256) k_sgemm(GemmP p) {
    int z = blockIdx.z;
    const float* __restrict__ A    = p.A[z];
    const float* __restrict__ Bm   = p.Bm[z];
    const float* __restrict__ Add  = p.Add[z];
    const float* __restrict__ bias = p.bias[z];
    float* __restrict__ C          = p.C[z];
    const int N = p.N, K = p.K, lda = p.lda;

    int n0 = blockIdx.x * 64, m0 = blockIdx.y * 64;
    __shared__ __align__(16) float As[16][68];
    __shared__ __align__(16) float Bs[16][64];

    int tid  = threadIdx.x;
    int tx   = tid & 15, ty = tid >> 4;
    int rowA = tid >> 2,  colA = (tid & 3) << 2;
    int rowB = tid >> 4,  colB = (tid & 15) << 2;

    const float* Aptr = A + (size_t)(m0 + rowA) * lda + colA;
    const float* Bptr = Bm + (size_t)rowB * N + n0 + colB;

    float acc[4][4] = {};
    for (int k0 = 0; k0 < K; k0 += 16) {
        float4 av = *(const float4*)(Aptr + k0);
        float4 bv = *(const float4*)(Bptr + (size_t)k0 * N);
        __syncthreads();
        As[colA + 0][rowA] = av.x;
        As[colA + 1][rowA] = av.y;
        As[colA + 2][rowA] = av.z;
        As[colA + 3][rowA] = av.w;
        *(float4*)&Bs[rowB][colB] = bv;
        __syncthreads();
#pragma unroll
        for (int k = 0; k < 16; k++) {
            float4 a = *(const float4*)&As[k][ty << 2];
            float4 b = *(const float4*)&Bs[k][tx << 2];
            acc[0][0] += a.x * b.x; acc[0][1] += a.x * b.y; acc[0][2] += a.x * b.z; acc[0][3] += a.x * b.w;
            acc[1][0] += a.y * b.x; acc[1][1] += a.y * b.y; acc[1][2] += a.y * b.z; acc[1][3] += a.y * b.w;
            acc[2][0] += a.z * b.x; acc[2][1] += a.z * b.y; acc[2][2] += a.z * b.z; acc[2][3] += a.z * b.w;
            acc[3][0] += a.w * b.x; acc[3][1] += a.w * b.y; acc[3][2] += a.w * b.z; acc[3][3] += a.w * b.w;
        }
    }
#pragma unroll
    for (int i = 0; i < 4; i++) {
        int m = m0 + (ty << 2) + i;
#pragma unroll
        for (int j = 0; j < 4; j++) {
            int n = n0 + (tx << 2) + j;
            float v = acc[i][j];
            if (Add)  v += Add[(size_t)m * p.ldAdd + n];
            if (bias) v += bias[n];
            C[(size_t)m * N + n] = v;
        }
    }
}

// ---------------------------------------------------------------------------
// LSTM pointwise cell. runs: 0:(e1,W1,s1) 1:(e2,W2,s2) 2:(e2,W1,s2) 3:(e1,W2,s1)
// ---------------------------------------------------------------------------
__device__ __forceinline__ float sigf(float x) { return 1.f / (1.f + expf(-x)); }

__global__ void k_lstm_cell(const float* __restrict__ G, float* __restrict__ c,
                            float* __restrict__ h, float* __restrict__ Y,
                            int t, const int* __restrict__ s1, const int* __restrict__ s2) {
    int i = blockIdx.x * blockDim.x + threadIdx.x;
    if (i >= 4 * B_ * H_) return;
    int r = i / (B_ * H_);
    int rem = i % (B_ * H_);
    int b = rem / H_, j = rem % H_;
    const float* g = G + ((size_t)r * B_ + b) * G4_;
    float gi = g[j], gj = g[H_ + j], gf = g[2 * H_ + j], go = g[3 * H_ + j];
    float cc = c[i];
    float cn = cc * sigf(gf + 1.f) + sigf(gi) * tanhf(gj);
    float hn = tanhf(cn) * sigf(go);
    int sl = (r == 0 || r == 3) ? s1[b] : s2[b];
    size_t yidx = (((size_t)r * B_ + b) * T_ + t) * H_ + j;
    if (t < sl) {
        c[i] = cn;
        h[i] = hn;
        Y[yidx] = hn;
    } else {
        Y[yidx] = 0.f;
    }
}

// ---------------------------------------------------------------------------
// Attention: init concat buffer [h_0 | r=0]
// ---------------------------------------------------------------------------
__global__ void k_att_init(float* __restrict__ aa, const float* __restrict__ Y) {
    int i = blockIdx.x * blockDim.x + threadIdx.x;
    if (i >= 2 * B_ * H_) return;
    int a = i / (B_ * H_);
    int rem = i % (B_ * H_);
    int b = rem / H_, hh = rem % H_;
    int run = a ? 3 : 1;  // Y2 run for each asym
    float* aab = aa + ((size_t)a * B_ + b) * 2 * H_;
    aab[hh]      = Y[(((size_t)run * B_ + b) * T_ + 0) * H_ + hh];
    aab[H_ + hh] = 0.f;
}

// ---------------------------------------------------------------------------
// Attention step: fused score/softmax/context/r-update. One CTA per (a,b).
// ---------------------------------------------------------------------------
__global__ void __launch_bounds__(512) k_att_step(
    int t, const float* __restrict__ WyY, const float* __restrict__ uP4,
    const float* __restrict__ wv, const float* __restrict__ Y,
    float* __restrict__ aa, float* __restrict__ rL,
    const int* __restrict__ s1, const int* __restrict__ s2) {
    int b = blockIdx.x, a = blockIdx.y;
    int tid = threadIdx.x, lane = tid & 31, w = tid >> 5;
    __shared__ float sc[64];
    __shared__ float su[512];   // u = h_t@Wh + r@Wr  (sum of 4 split-K partials)
    __shared__ float spt[512];  // pre_tr = r@Wt

    for (int col = tid; col < 1024; col += 512) {
        float s = 0.f;
#pragma unroll
        for (int ch = 0; ch < 4; ch++)
            s += uP4[(((size_t)a * 4 + ch) * B_ + b) * 1024 + col];
        if (col < 512) su[col] = s; else spt[col - 512] = s;
    }
    __syncthreads();

    // Phase 1: scores over t2 (16 warps x 4 each)
    const float* WyYb = WyY + ((size_t)a * B_ + b) * T_ * H_;
#pragma unroll
    for (int q = 0; q < 4; q++) {
        int t2 = (w << 2) + q;
        const float* row = WyYb + (size_t)t2 * H_;
        float s = 0.f;
#pragma unroll
        for (int hh = lane; hh < H_; hh += 32)
            s += tanhf(row[hh] + su[hh]) * wv[hh];
        for (int o = 16; o; o >>= 1) s += __shfl_xor_sync(0xffffffffu, s, o);
        if (lane == 0) {
            int sl = a ? s2[b] : s1[b];  // mask follows Y's seqlen
            sc[t2] = s + (t2 < sl ? 0.f : -10000.f);
        }
    }
    __syncthreads();

    // Phase 2: softmax over 64 (warp 0)
    if (w == 0) {
        float v1 = sc[lane], v2 = sc[lane + 32];
        float m = fmaxf(v1, v2);
        for (int o = 16; o; o >>= 1) m = fmaxf(m, __shfl_xor_sync(0xffffffffu, m, o));
        float e1 = expf(v1 - m), e2 = expf(v2 - m);
        float s = e1 + e2;
        for (int o = 16; o; o >>= 1) s += __shfl_xor_sync(0xffffffffu, s, o);
        float inv = 1.f / s;
        sc[lane] = e1 * inv;
        sc[lane + 32] = e2 * inv;
    }
    __syncthreads();

    // Phase 3: context + r update; stage next step's [h_{t+1} | r_new]
    int hh = tid;
    int runY = a ? 2 : 0;
    const float* Yb = Y + ((size_t)runY * B_ + b) * T_ * H_ + hh;
    float acc = 0.f;
#pragma unroll
    for (int t2 = 0; t2 < T_; t2++) acc += sc[t2] * Yb[(size_t)t2 * H_];
    float rn = acc + tanhf(spt[hh]);
    int sl2 = a ? s1[b] : s2[b];  // r_L index follows Y2's seqlen
    if (t == sl2 - 1) rL[((size_t)a * B_ + b) * H_ + hh] = rn;
    float* aab = aa + ((size_t)a * B_ + b) * 2 * H_;
    if (t + 1 < T_) {
        int runY2 = a ? 3 : 1;
        aab[hh]      = Y[(((size_t)runY2 * B_ + b) * T_ + (t + 1)) * H_ + hh];
        aab[H_ + hh] = rn;
    }
}

// ---------------------------------------------------------------------------
// Final: la/lb = tanh(rL@Wp + last_h@Wx); out = (la+lb)@U + bU
// ---------------------------------------------------------------------------
__global__ void __launch_bounds__(512) k_final(
    const float* __restrict__ rL, const float* __restrict__ hfin,
    const float* __restrict__ Wp, const float* __restrict__ Wx,
    const float* __restrict__ U, const float* __restrict__ bU,
    float* __restrict__ out) {
    int b = blockIdx.x;
    int tid = threadIdx.x;
    __shared__ float s_in[4][512];
    __shared__ float s_sum[512];
    __shared__ float red0[16], red1[16];
    s_in[0][tid] = rL[(size_t)b * H_ + tid];                 // r_L (la)
    s_in[1][tid] = hfin[((size_t)1 * B_ + b) * H_ + tid];    // last_h run1 (la)
    s_in[2][tid] = rL[((size_t)B_ + b) * H_ + tid];          // r_L (lb)
    s_in[3][tid] = hfin[((size_t)3 * B_ + b) * H_ + tid];    // last_h run3 (lb)
    __syncthreads();
    float acc0 = 0.f, acc1 = 0.f;
    for (int k = 0; k < H_; k++) {
        float wp = Wp[(size_t)k * H_ + tid];
        float wx = Wx[(size_t)k * H_ + tid];
        acc0 += s_in[0][k] * wp + s_in[1][k] * wx;
        acc1 += s_in[2][k] * wp + s_in[3][k] * wx;
    }
    s_sum[tid] = tanhf(acc0) + tanhf(acc1);
    __syncthreads();
    float p0 = s_sum[tid] * U[(size_t)tid * 2 + 0];
    float p1 = s_sum[tid] * U[(size_t)tid * 2 + 1];
    for (int o = 16; o; o >>= 1) {
        p0 += __shfl_xor_sync(0xffffffffu, p0, o);
        p1 += __shfl_xor_sync(0xffffffffu, p1, o);
    }
    int wp_ = tid >> 5;
    if ((tid & 31) == 0) { red0[wp_] = p0; red1[wp_] = p1; }
    __syncthreads();
    if (tid < 16) {
        p0 = red0[tid]; p1 = red1[tid];
        for (int o = 8; o; o >>= 1) {
            p0 += __shfl_xor_sync(0x0000ffffu, p0, o);
            p1 += __shfl_xor_sync(0x0000ffffu, p1, o);
        }
        if (tid == 0) {
            out[b * 2 + 0] = p0 + bU[0];
            out[b * 2 + 1] = p1 + bU[1];
        }
    }
}

// ---------------------------------------------------------------------------
// Host orchestration
// ---------------------------------------------------------------------------
extern "C" void kernel_launch(void* const* d_in, const int* in_sizes, int n_in,
                              void* d_out, int out_size) {
    (void)in_sizes; (void)n_in; (void)out_size;
    const int*   tokens1 = (const int*)d_in[0];
    const int*   tokens2 = (const int*)d_in[1];
    const int*   seqlen1 = (const int*)d_in[2];
    const int*   seqlen2 = (const int*)d_in[3];
    const float* emb = (const float*)d_in[4];
    const float* W1  = (const float*)d_in[5];
    const float* b1  = (const float*)d_in[6];
    const float* W2  = (const float*)d_in[7];
    const float* b2  = (const float*)d_in[8];
    const float* Wy  = (const float*)d_in[9];
    const float* Wh  = (const float*)d_in[10];
    const float* Wr  = (const float*)d_in[11];
    const float* wv  = (const float*)d_in[12];
    const float* Wt  = (const float*)d_in[13];
    const float* Wp  = (const float*)d_in[14];
    const float* Wx  = (const float*)d_in[15];
    const float* U   = (const float*)d_in[16];
    const float* bU  = (const float*)d_in[17];
    float* out = (float*)d_out;

    float* buf = nullptr;
    cudaGetSymbolAddress((void**)&buf, d_buf);
    float* e   = buf + OFF_E;
    float* WxP = buf + OFF_WXP;
    float* Xg  = buf + OFF_XG;
    float* Yb  = buf + OFF_Y;
    float* hS  = buf + OFF_H;
    float* cS  = buf + OFF_C;
    float* G   = buf + OFF_G;
    float* WyY = buf + OFF_WYY;
    float* Wc  = buf + OFF_WC;
    float* uP4 = buf + OFF_UP;
    float* aa  = buf + OFF_AA;
    float* rL  = buf + OFF_RL;

    k_prep<<<512, 256>>>(WxP, Wc, W1, W2, Wh, Wr, Wt);
    k_gather<<<2048, 256>>>(e, tokens1, tokens2, emb);
    k_zero<<<1024, 256>>>(hS, 2ull * 4 * B_ * H_);  // h and c are contiguous

    // X-part: Xg[r] = E_{i(r)} @ WxP_{w(r)} + b_{w(r)}
    {
        GemmP p = {};
        int iidx[4] = {0, 1, 1, 0}, widx[4] = {0, 1, 0, 1};
        for (int r = 0; r < 4; r++) {
            p.A[r]    = e + (size_t)iidx[r] * B_ * T_ * KP_;
            p.Bm[r]   = WxP + (size_t)widx[r] * KP_ * G4_;
            p.Add[r]  = nullptr;
            p.bias[r] = widx[r] ? b2 : b1;
            p.C[r]    = Xg + (size_t)r * B_ * T_ * G4_;
        }
        p.M = B_ * T_; p.N = G4_; p.K = KP_; p.lda = KP_; p.ldAdd = 0;
        k_sgemm<<<dim3(G4_ / 64, (B_ * T_) / 64, 4), 256>>>(p);
    }

    // LSTM scan: 64 steps x (recurrent GEMM + cell)
    for (int t = 0; t < T_; t++) {
        GemmP p = {};
        for (int r = 0; r < 4; r++) {
            p.A[r]    = hS + (size_t)r * B_ * H_;
            p.Bm[r]   = ((r == 0 || r == 2) ? W1 : W2) + (size_t)D_ * G4_;
            p.Add[r]  = Xg + (size_t)r * B_ * T_ * G4_ + (size_t)t * G4_;
            p.bias[r] = nullptr;
            p.C[r]    = G + (size_t)r * B_ * G4_;
        }
        p.M = B_; p.N = G4_; p.K = H_; p.lda = H_; p.ldAdd = T_ * G4_;
        k_sgemm<<<dim3(G4_ / 64, B_ / 64, 4), 256>>>(p);
        k_lstm_cell<<<(4 * B_ * H_) / 256, 256>>>(G, cS, hS, Yb, t, seqlen1, seqlen2);
    }

    // WyY[a] = Y_a @ Wy
    {
        GemmP p = {};
        for (int a = 0; a < 2; a++) {
            p.A[a]    = Yb + (size_t)(a ? 2 : 0) * B_ * T_ * H_;
            p.Bm[a]   = Wy;
            p.Add[a]  = nullptr;
            p.bias[a] = nullptr;
            p.C[a]    = WyY + (size_t)a * B_ * T_ * H_;
        }
        p.M = B_ * T_; p.N = H_; p.K = H_; p.lda = H_; p.ldAdd = 0;
        k_sgemm<<<dim3(H_ / 64, (B_ * T_) / 64, 2), 256>>>(p);
    }

    k_att_init<<<(2 * B_ * H_) / 256, 256>>>(aa, Yb);

    // Attention scan: 64 steps x (split-K GEMM + fused step kernel)
    for (int t = 0; t < T_; t++) {
        GemmP p = {};
        for (int z = 0; z < 8; z++) {
            int a = z >> 2, ch = z & 3;
            p.A[z]    = aa + (size_t)a * B_ * 2 * H_ + (size_t)ch * 256;
            p.Bm[z]   = Wc + (size_t)ch * 256 * 1024;
            p.Add[z]  = nullptr;
            p.bias[z] = nullptr;
            p.C[z]    = uP4 + (size_t)z * B_ * 1024;
        }
        p.M = B_; p.N = 1024; p.K = 256; p.lda = 2 * H_; p.ldAdd = 0;
        k_sgemm<<<dim3(1024 / 64, B_ / 64, 8), 256>>>(p);
        k_att_step<<<dim3(B_, 2), 512>>>(t, WyY, uP4, wv, Yb, aa, rL, seqlen1, seqlen2);
    }

    k_final<<<B_, 512>>>(rL, hS, Wp, Wx, U, bU, out);
}